// round 10
// baseline (speedup 1.0000x reference)
#include <cuda_runtime.h>

typedef unsigned long long u64;

#define BB   64
#define TIN  1024
#define T1   1020
#define T2   1016
#define HH   12
#define LL   120
#define GG   48
#define RING 64
#define RM   (RING-1)
#define CH   4           /* sync chunk: steps per flag release */
#define BH   (BB*HH)     /* 768 */
#define OUTSZ (BB*LL*HH) /* 92160 */
#define NW   8           /* warps per layer CTA */

// ---------------- device scratch (static, no allocation) ----------------
__device__ float g_y1[BB*6*T1];
__device__ float g_y2[BB*6*T2];
__device__ float g_part1[BB*12];
__device__ float g_part2[BB*12];
__device__ float g_feat[T2*BH];
__device__ float g_ring[(LL-1)*RING*BH];
__device__ float g_hlast[LL*BH];
__device__ int   g_progress[LL*NW];

// ---------------- helpers ----------------
__device__ __forceinline__ int ld_acq(const int* p){
  int v; asm volatile("ld.acquire.gpu.b32 %0, [%1];" : "=r"(v) : "l"(p)); return v;
}
__device__ __forceinline__ void st_rel(int* p, int v){
  asm volatile("st.release.gpu.b32 [%0], %1;" :: "l"(p), "r"(v));
}
__device__ __forceinline__ u64 pk2(float lo, float hi){
  u64 r; asm("mov.b64 %0, {%1, %2};" : "=l"(r) : "f"(lo), "f"(hi)); return r;
}
__device__ __forceinline__ void upk2(u64 v, float& lo, float& hi){
  asm("mov.b64 {%0, %1}, %2;" : "=f"(lo), "=f"(hi) : "l"(v));
}
__device__ __forceinline__ void ffma2(u64& acc, u64 a, u64 b){
  asm("fma.rn.f32x2 %0, %1, %2, %0;" : "+l"(acc) : "l"(a), "l"(b));
}
// hardware tanh (sm_75+): single MUFU op
__device__ __forceinline__ float tanhfast(float x){
  float y; asm("tanh.approx.f32 %0, %1;" : "=f"(y) : "f"(x)); return y;
}

// ---------------- conv1 + batch-stat partials (+ pipeline-flag reset) ------
__global__ void k_conv1(const float* __restrict__ x, const float* __restrict__ w,
                        const float* __restrict__ bias){
  __shared__ float xs[6*TIN];
  __shared__ float ws[180];
  __shared__ float bs[6];
  __shared__ float red[12][8];
  int b = blockIdx.x, tid = threadIdx.x;
  if (b == 0){                       // flag reset (read only by later k_lstm)
    for (int i = tid; i < LL*NW; i += 256) g_progress[i] = 0;
  }
  for (int i = tid; i < 6*TIN; i += 256) xs[i] = x[b*6*TIN + i];
  for (int i = tid; i < 180;   i += 256) ws[i] = w[i];
  if (tid < 6) bs[tid] = bias[tid];
  __syncthreads();
  float s[6] = {0,0,0,0,0,0}, q[6] = {0,0,0,0,0,0};
  for (int t = tid; t < T1; t += 256){
    float acc[6];
    #pragma unroll
    for (int co = 0; co < 6; co++) acc[co] = bs[co];
    #pragma unroll
    for (int ci = 0; ci < 6; ci++){
      float xr[5];
      #pragma unroll
      for (int k = 0; k < 5; k++) xr[k] = xs[ci*TIN + t + k];
      #pragma unroll
      for (int co = 0; co < 6; co++){
        const float* wp = &ws[co*30 + ci*5];
        #pragma unroll
        for (int k = 0; k < 5; k++) acc[co] += xr[k]*wp[k];
      }
    }
    #pragma unroll
    for (int co = 0; co < 6; co++){
      g_y1[b*6*T1 + co*T1 + t] = acc[co];
      s[co] += acc[co]; q[co] += acc[co]*acc[co];
    }
  }
  int lane = tid & 31, wrp = tid >> 5;
  #pragma unroll
  for (int c = 0; c < 6; c++){
    float v = s[c], u = q[c];
    #pragma unroll
    for (int o = 16; o; o >>= 1){
      v += __shfl_down_sync(0xffffffffu, v, o);
      u += __shfl_down_sync(0xffffffffu, u, o);
    }
    if (lane == 0){ red[c][wrp] = v; red[6+c][wrp] = u; }
  }
  __syncthreads();
  if (tid < 12){
    float a = 0.f;
    #pragma unroll
    for (int w8 = 0; w8 < 8; w8++) a += red[tid][w8];
    g_part1[b*12 + tid] = a;
  }
}

// ---------------- bn1+relu -> conv2 + stat partials ----------------
__global__ void k_conv2(const float* __restrict__ w, const float* __restrict__ bias,
                        const float* __restrict__ gamma, const float* __restrict__ beta){
  __shared__ float xs[6*T1];
  __shared__ float ws[180];
  __shared__ float bs[6];
  __shared__ float stt[12];
  __shared__ float sc[6], sh[6];
  __shared__ float red[12][8];
  int b = blockIdx.x, tid = threadIdx.x;
  if (tid < 12){
    float a = 0.f;
    for (int bb = 0; bb < BB; bb++) a += g_part1[bb*12 + tid];
    stt[tid] = a;
  }
  for (int i = tid; i < 180; i += 256) ws[i] = w[i];
  if (tid < 6) bs[tid] = bias[tid];
  __syncthreads();
  if (tid < 6){
    float inv  = 1.f / (64.f * 1020.f);
    float mean = stt[tid]*inv;
    float var  = stt[6+tid]*inv - mean*mean;
    float scl  = gamma[tid]*rsqrtf(var + 1e-5f);
    sc[tid] = scl; sh[tid] = beta[tid] - mean*scl;
  }
  __syncthreads();
  for (int i = tid; i < 6*T1; i += 256){
    int c = i / T1;
    float v = g_y1[b*6*T1 + i]*sc[c] + sh[c];
    xs[i] = fmaxf(v, 0.f);
  }
  __syncthreads();
  float s[6] = {0,0,0,0,0,0}, q[6] = {0,0,0,0,0,0};
  for (int t = tid; t < T2; t += 256){
    float acc[6];
    #pragma unroll
    for (int co = 0; co < 6; co++) acc[co] = bs[co];
    #pragma unroll
    for (int ci = 0; ci < 6; ci++){
      float xr[5];
      #pragma unroll
      for (int k = 0; k < 5; k++) xr[k] = xs[ci*T1 + t + k];
      #pragma unroll
      for (int co = 0; co < 6; co++){
        const float* wp = &ws[co*30 + ci*5];
        #pragma unroll
        for (int k = 0; k < 5; k++) acc[co] += xr[k]*wp[k];
      }
    }
    #pragma unroll
    for (int co = 0; co < 6; co++){
      g_y2[b*6*T2 + co*T2 + t] = acc[co];
      s[co] += acc[co]; q[co] += acc[co]*acc[co];
    }
  }
  int lane = tid & 31, wrp = tid >> 5;
  #pragma unroll
  for (int c = 0; c < 6; c++){
    float v = s[c], u = q[c];
    #pragma unroll
    for (int o = 16; o; o >>= 1){
      v += __shfl_down_sync(0xffffffffu, v, o);
      u += __shfl_down_sync(0xffffffffu, u, o);
    }
    if (lane == 0){ red[c][wrp] = v; red[6+c][wrp] = u; }
  }
  __syncthreads();
  if (tid < 12){
    float a = 0.f;
    #pragma unroll
    for (int w8 = 0; w8 < 8; w8++) a += red[tid][w8];
    g_part2[b*12 + tid] = a;
  }
}

// ---------------- bn2+relu -> attn projection -> feat[t][b][h] ----------------
__global__ void k_attn(const float* __restrict__ gamma, const float* __restrict__ beta,
                       const float* __restrict__ aw, const float* __restrict__ ab){
  __shared__ float xs[6*T2];
  __shared__ float stt[12];
  __shared__ float sc[6], sh[6];
  __shared__ float aws[72];
  __shared__ float abv[12];
  int b = blockIdx.x, tid = threadIdx.x;
  if (tid < 12){
    float a = 0.f;
    for (int bb = 0; bb < BB; bb++) a += g_part2[bb*12 + tid];
    stt[tid] = a;
  }
  if (tid < 72) aws[tid] = aw[tid];
  if (tid < 12) abv[tid] = ab[tid];
  __syncthreads();
  if (tid < 6){
    float inv  = 1.f / (64.f * 1016.f);
    float mean = stt[tid]*inv;
    float var  = stt[6+tid]*inv - mean*mean;
    float scl  = gamma[tid]*rsqrtf(var + 1e-5f);
    sc[tid] = scl; sh[tid] = beta[tid] - mean*scl;
  }
  __syncthreads();
  for (int i = tid; i < 6*T2; i += 256){
    int c = i / T2;
    float v = g_y2[b*6*T2 + i]*sc[c] + sh[c];
    xs[i] = fmaxf(v, 0.f);
  }
  __syncthreads();
  for (int i = tid; i < T2*HH; i += 256){
    int t = i / HH, h = i % HH;
    float acc = abv[h];
    #pragma unroll
    for (int c = 0; c < 6; c++) acc += xs[c*T2 + t]*aws[h*6 + c];
    g_feat[t*BH + b*12 + h] = fmaxf(acc, 0.f);
  }
}

// ---------------- pipelined 120-layer LSTM, warp-granular, chunked sync -----
// 1 layer per CTA. Lane-group of 4 owns one batch element (b = tid>>2,
// q = tid&3, cells 3q..3q+2); h exchanged via shfl. Warp w syncs only with
// warp w of neighbor layers via per-warp release/acquire flags.
// R9: CHUNKED sync (CH=4): one flag wait + one release per 4 steps; inside
// a chunk input availability is certain -> deterministic prefetch, zero
// per-step flag traffic.
__global__ void __launch_bounds__(256,1) k_lstm(const float* __restrict__ wih,
                                                const float* __restrict__ whh,
                                                const float* __restrict__ bih,
                                                const float* __restrict__ bhh){
  int l = blockIdx.x, tid = threadIdx.x;
  int lane = tid & 31;
  int wz   = tid >> 5;          // warp id 0..7
  int q    = lane & 3;          // quarter within batch group
  int b    = tid >> 2;          // batch element 0..63

  __shared__ __align__(16) u64 wpk[GG][12];  // packed {w_k,w_{k+1}} per gate row over [x;h]

  const float* wi = wih + l*576;
  const float* wh = whh + l*576;
  for (int i = tid; i < GG*12; i += 256){
    int gg = i / 12, kp = i % 12;
    float w0, w1;
    if (kp < 6){ w0 = wi[gg*12 + 2*kp];      w1 = wi[gg*12 + 2*kp + 1];  }
    else       { w0 = wh[gg*12 + 2*kp - 12]; w1 = wh[gg*12 + 2*kp - 11]; }
    wpk[gg][kp] = pk2(w0, w1);
  }
  __syncthreads();

  // register-cache rows of gates 0 and 1 (cells 3q..3q+2): 6 rows x 12 u64
  u64 wr[6][12];
  #pragma unroll
  for (int g4 = 0; g4 < 2; g4++)
    #pragma unroll
    for (int j = 0; j < 3; j++)
      #pragma unroll
      for (int k = 0; k < 12; k++)
        wr[g4*3+j][k] = wpk[g4*12 + 3*q + j][k];

  // biases; gates 0,1,3 (sigmoid) pre-scaled by 0.5 for the tanh identity
  float br[12];
  #pragma unroll
  for (int j = 0; j < 3; j++){
    #pragma unroll
    for (int g4 = 0; g4 < 4; g4++){
      int row = g4*12 + 3*q + j;
      float bv = bih[l*GG + row] + bhh[l*GG + row];
      br[j*4+g4] = (g4 == 2) ? bv : 0.5f*bv;
    }
  }

  float c0 = 0.f, c1 = 0.f, c2 = 0.f;
  float hl0 = 0.f, hl1 = 0.f, hl2 = 0.f;
  float*       ringo = (l < LL-1) ? (g_ring + (size_t)l*(RING*BH)) : (float*)0;
  const float* ringi = (l > 0)    ? (g_ring + (size_t)(l-1)*(RING*BH)) : (const float*)0;
  const int* flag_in  = (l > 0)    ? &g_progress[(l-1)*NW + wz] : (const int*)0;
  const int* flag_out = (l < LL-1) ? &g_progress[(l+1)*NW + wz] : (const int*)0;
  int* flag_me = &g_progress[l*NW + wz];

  int last_in = 0, last_out = 0;
  float4 pa, pb, pc;

  for (int t0 = 0; t0 < T2; t0 += CH){
    // ---- chunk-level input wait (only flag read of the chunk) ----
    if (l > 0 && last_in < t0 + CH){
      do { last_in = ld_acq(flag_in); } while (last_in < t0 + CH);
    }
    // ---- chunk-level backpressure ----
    if (l < LL-1 && t0 + CH > RING && last_out + RING < t0 + CH){
      do { last_out = ld_acq(flag_out); } while (last_out + RING < t0 + CH);
    }

    #pragma unroll
    for (int tt = 0; tt < CH; tt++){
      int t = t0 + tt;

      // ---- gather previous h of this batch element via 4-lane shfl ----
      float h_all[12];
      #pragma unroll
      for (int qp = 0; qp < 4; qp++){
        int src = (lane & ~3) | qp;
        h_all[3*qp+0] = __shfl_sync(0xffffffffu, hl0, src);
        h_all[3*qp+1] = __shfl_sync(0xffffffffu, hl1, src);
        h_all[3*qp+2] = __shfl_sync(0xffffffffu, hl2, src);
      }
      u64 xv[12];
      #pragma unroll
      for (int m = 0; m < 6; m++) xv[6+m] = pk2(h_all[2*m], h_all[2*m+1]);

      // ---- input: first step of chunk loads directly, rest prefetched ----
      float4 xa, xb, xc;
      if (tt == 0){
        const float* src = (l == 0) ? (g_feat + (size_t)t*BH + b*12)
                                    : (ringi + (size_t)(t & RM)*BH + b*12);
        xa = __ldcg((const float4*)(src));
        xb = __ldcg((const float4*)(src + 4));
        xc = __ldcg((const float4*)(src + 8));
      } else { xa = pa; xb = pb; xc = pc; }
      xv[0] = pk2(xa.x, xa.y); xv[1] = pk2(xa.z, xa.w);
      xv[2] = pk2(xb.x, xb.y); xv[3] = pk2(xb.z, xb.w);
      xv[4] = pk2(xc.x, xc.y); xv[5] = pk2(xc.z, xc.w);

      // ---- deterministic prefetch of next step within the chunk ----
      if (tt < CH-1){
        const float* src2 = (l == 0) ? (g_feat + (size_t)(t+1)*BH + b*12)
                                     : (ringi + (size_t)((t+1) & RM)*BH + b*12);
        pa = __ldcg((const float4*)(src2));
        pb = __ldcg((const float4*)(src2 + 4));
        pc = __ldcg((const float4*)(src2 + 8));
      }

      // ---- 12 gate pre-activations: gates 0,1 from registers ----
      float gv[12];
      #pragma unroll
      for (int g4 = 0; g4 < 2; g4++){
        #pragma unroll
        for (int j = 0; j < 3; j++){
          u64 acc = 0ull;
          #pragma unroll
          for (int k = 0; k < 12; k++) ffma2(acc, wr[g4*3+j][k], xv[k]);
          float lo, hi; upk2(acc, lo, hi);
          gv[j*4+g4] = fmaf(lo + hi, 0.5f, br[j*4+g4]);
        }
      }
      // ---- gates 2,3 from shared memory ----
      #pragma unroll
      for (int g4 = 2; g4 < 4; g4++){
        #pragma unroll
        for (int j = 0; j < 3; j++){
          const ulonglong2* wrow = (const ulonglong2*)(&wpk[g4*12 + 3*q + j][0]);
          u64 acc = 0ull;
          #pragma unroll
          for (int kq = 0; kq < 6; kq++){
            ulonglong2 wv = wrow[kq];
            ffma2(acc, wv.x, xv[2*kq]);
            ffma2(acc, wv.y, xv[2*kq+1]);
          }
          float lo, hi; upk2(acc, lo, hi);
          gv[j*4+g4] = (g4 == 2) ? (lo + hi + br[j*4+g4])
                                 : fmaf(lo + hi, 0.5f, br[j*4+g4]);
        }
      }

      // ---- activations (HW tanh) + cell update ----
      {
        float ig = fmaf(0.5f, tanhfast(gv[0]), 0.5f);
        float fg = fmaf(0.5f, tanhfast(gv[1]), 0.5f);
        float zg = tanhfast(gv[2]);
        float og = fmaf(0.5f, tanhfast(gv[3]), 0.5f);
        c0 = fg*c0 + ig*zg; hl0 = og*tanhfast(c0);
      }
      {
        float ig = fmaf(0.5f, tanhfast(gv[4]), 0.5f);
        float fg = fmaf(0.5f, tanhfast(gv[5]), 0.5f);
        float zg = tanhfast(gv[6]);
        float og = fmaf(0.5f, tanhfast(gv[7]), 0.5f);
        c1 = fg*c1 + ig*zg; hl1 = og*tanhfast(c1);
      }
      {
        float ig = fmaf(0.5f, tanhfast(gv[8]), 0.5f);
        float fg = fmaf(0.5f, tanhfast(gv[9]), 0.5f);
        float zg = tanhfast(gv[10]);
        float og = fmaf(0.5f, tanhfast(gv[11]), 0.5f);
        c2 = fg*c2 + ig*zg; hl2 = og*tanhfast(c2);
      }

      // ---- publish data stores (flag released once per chunk) ----
      if (l < LL-1){
        float* dst = ringo + (size_t)(t & RM)*BH + b*12 + 3*q;
        __stcg(dst,     hl0);
        __stcg(dst + 1, hl1);
        __stcg(dst + 2, hl2);
      }
    }

    __syncwarp();
    if (lane == 0) st_rel(flag_me, t0 + CH);
  }

  int base = l*BH + b*12 + 3*q;
  g_hlast[base]     = hl0;
  g_hlast[base + 1] = hl1;
  g_hlast[base + 2] = hl2;
}

// ---------------- head: lin1/lin2 -> out, mu, softplus(sigma) ----------------
__global__ void k_head(const float* __restrict__ l1w, const float* __restrict__ l1b,
                       const float* __restrict__ l2w, const float* __restrict__ l2b,
                       const float* __restrict__ muw, const float* __restrict__ mub,
                       const float* __restrict__ sgw, const float* __restrict__ sgb,
                       float* __restrict__ out){
  int idx = blockIdx.x*blockDim.x + threadIdx.x;
  if (idx >= BB*LL) return;
  int b = idx / LL, l = idx % LL;
  const float* hv = g_hlast + l*BH + b*12;
  float h0[12], h1[12], h2[12];
  #pragma unroll
  for (int k = 0; k < 12; k++) h0[k] = hv[k];
  #pragma unroll
  for (int i = 0; i < 12; i++){
    float a = l1b[i];
    #pragma unroll
    for (int j = 0; j < 12; j++) a += l1w[i*12+j]*h0[j];
    h1[i] = fmaxf(a, 0.f);
  }
  #pragma unroll
  for (int i = 0; i < 12; i++){
    float a = l2b[i];
    #pragma unroll
    for (int j = 0; j < 12; j++) a += l2w[i*12+j]*h1[j];
    h2[i] = fmaxf(a, 0.f);
  }
  int base = (b*LL + l)*12;
  #pragma unroll
  for (int i = 0; i < 12; i++) out[base + i] = h2[i];
  #pragma unroll
  for (int i = 0; i < 12; i++){
    float a = mub[i];
    #pragma unroll
    for (int j = 0; j < 12; j++) a += muw[i*12+j]*h2[j];
    out[OUTSZ + base + i] = a;
  }
  #pragma unroll
  for (int i = 0; i < 12; i++){
    float a = sgb[i];
    #pragma unroll
    for (int j = 0; j < 12; j++) a += sgw[i*12+j]*h2[j];
    out[2*OUTSZ + base + i] = fmaxf(a, 0.f) + log1pf(__expf(-fabsf(a)));
  }
}

extern "C" void kernel_launch(void* const* d_in, const int* in_sizes, int n_in,
                              void* d_out, int out_size) {
  const float* x     = (const float*)d_in[0];
  const float* c1w   = (const float*)d_in[1];
  const float* c1b   = (const float*)d_in[2];
  const float* bn1g  = (const float*)d_in[3];
  const float* bn1b  = (const float*)d_in[4];
  const float* c2w   = (const float*)d_in[5];
  const float* c2b   = (const float*)d_in[6];
  const float* bn2g  = (const float*)d_in[7];
  const float* bn2b  = (const float*)d_in[8];
  const float* aw    = (const float*)d_in[9];
  const float* ab    = (const float*)d_in[10];
  const float* wih   = (const float*)d_in[11];
  const float* whh   = (const float*)d_in[12];
  const float* bih   = (const float*)d_in[13];
  const float* bhh   = (const float*)d_in[14];
  const float* l1w   = (const float*)d_in[15];
  const float* l1b   = (const float*)d_in[16];
  const float* l2w   = (const float*)d_in[17];
  const float* l2b   = (const float*)d_in[18];
  const float* muw   = (const float*)d_in[19];
  const float* mub   = (const float*)d_in[20];
  const float* sgw   = (const float*)d_in[21];
  const float* sgb   = (const float*)d_in[22];
  float* out = (float*)d_out;

  k_conv1<<<BB, 256>>>(x, c1w, c1b);
  k_conv2<<<BB, 256>>>(c2w, c2b, bn1g, bn1b);
  k_attn<<<BB, 256>>>(bn2g, bn2b, aw, ab);
  k_lstm<<<LL, 256>>>(wih, whh, bih, bhh);
  k_head<<<(BB*LL + 127)/128, 128>>>(l1w, l1b, l2w, l2b, muw, mub, sgw, sgb, out);
}

// round 11
// speedup vs baseline: 1.0280x; 1.0280x over previous
#include <cuda_runtime.h>

typedef unsigned long long u64;

#define BB   64
#define TIN  1024
#define T1   1020
#define T2   1016
#define HH   12
#define LL   120
#define GG   48
#define RING 64
#define RM   (RING-1)
#define BH   (BB*HH)     /* 768 */
#define OUTSZ (BB*LL*HH) /* 92160 */
#define NW   16          /* warps per layer CTA (512 threads) */

// ---------------- device scratch (static, no allocation) ----------------
__device__ float g_y1[BB*6*T1];
__device__ float g_y2[BB*6*T2];
__device__ float g_part1[BB*12];
__device__ float g_part2[BB*12];
__device__ float g_feat[T2*BH];
__device__ float g_ring[(LL-1)*RING*BH];
__device__ float g_hlast[LL*BH];
__device__ int   g_progress[LL*NW];

// ---------------- helpers ----------------
__device__ __forceinline__ int ld_acq(const int* p){
  int v; asm volatile("ld.acquire.gpu.b32 %0, [%1];" : "=r"(v) : "l"(p)); return v;
}
__device__ __forceinline__ void st_rel(int* p, int v){
  asm volatile("st.release.gpu.b32 [%0], %1;" :: "l"(p), "r"(v));
}
__device__ __forceinline__ u64 pk2(float lo, float hi){
  u64 r; asm("mov.b64 %0, {%1, %2};" : "=l"(r) : "f"(lo), "f"(hi)); return r;
}
__device__ __forceinline__ void upk2(u64 v, float& lo, float& hi){
  asm("mov.b64 {%0, %1}, %2;" : "=f"(lo), "=f"(hi) : "l"(v));
}
__device__ __forceinline__ void ffma2(u64& acc, u64 a, u64 b){
  asm("fma.rn.f32x2 %0, %1, %2, %0;" : "+l"(acc) : "l"(a), "l"(b));
}
// hardware tanh (sm_75+): single MUFU op
__device__ __forceinline__ float tanhfast(float x){
  float y; asm("tanh.approx.f32 %0, %1;" : "=f"(y) : "f"(x)); return y;
}

// ---------------- conv1 + batch-stat partials (+ pipeline-flag reset) ------
__global__ void k_conv1(const float* __restrict__ x, const float* __restrict__ w,
                        const float* __restrict__ bias){
  __shared__ float xs[6*TIN];
  __shared__ float ws[180];
  __shared__ float bs[6];
  __shared__ float red[12][8];
  int b = blockIdx.x, tid = threadIdx.x;
  if (b == 0){                       // flag reset (read only by later k_lstm)
    for (int i = tid; i < LL*NW; i += 256) g_progress[i] = 0;
  }
  for (int i = tid; i < 6*TIN; i += 256) xs[i] = x[b*6*TIN + i];
  for (int i = tid; i < 180;   i += 256) ws[i] = w[i];
  if (tid < 6) bs[tid] = bias[tid];
  __syncthreads();
  float s[6] = {0,0,0,0,0,0}, q[6] = {0,0,0,0,0,0};
  for (int t = tid; t < T1; t += 256){
    float acc[6];
    #pragma unroll
    for (int co = 0; co < 6; co++) acc[co] = bs[co];
    #pragma unroll
    for (int ci = 0; ci < 6; ci++){
      float xr[5];
      #pragma unroll
      for (int k = 0; k < 5; k++) xr[k] = xs[ci*TIN + t + k];
      #pragma unroll
      for (int co = 0; co < 6; co++){
        const float* wp = &ws[co*30 + ci*5];
        #pragma unroll
        for (int k = 0; k < 5; k++) acc[co] += xr[k]*wp[k];
      }
    }
    #pragma unroll
    for (int co = 0; co < 6; co++){
      g_y1[b*6*T1 + co*T1 + t] = acc[co];
      s[co] += acc[co]; q[co] += acc[co]*acc[co];
    }
  }
  int lane = tid & 31, wrp = tid >> 5;
  #pragma unroll
  for (int c = 0; c < 6; c++){
    float v = s[c], u = q[c];
    #pragma unroll
    for (int o = 16; o; o >>= 1){
      v += __shfl_down_sync(0xffffffffu, v, o);
      u += __shfl_down_sync(0xffffffffu, u, o);
    }
    if (lane == 0){ red[c][wrp] = v; red[6+c][wrp] = u; }
  }
  __syncthreads();
  if (tid < 12){
    float a = 0.f;
    #pragma unroll
    for (int w8 = 0; w8 < 8; w8++) a += red[tid][w8];
    g_part1[b*12 + tid] = a;
  }
}

// ---------------- bn1+relu -> conv2 + stat partials ----------------
__global__ void k_conv2(const float* __restrict__ w, const float* __restrict__ bias,
                        const float* __restrict__ gamma, const float* __restrict__ beta){
  __shared__ float xs[6*T1];
  __shared__ float ws[180];
  __shared__ float bs[6];
  __shared__ float stt[12];
  __shared__ float sc[6], sh[6];
  __shared__ float red[12][8];
  int b = blockIdx.x, tid = threadIdx.x;
  if (tid < 12){
    float a = 0.f;
    for (int bb = 0; bb < BB; bb++) a += g_part1[bb*12 + tid];
    stt[tid] = a;
  }
  for (int i = tid; i < 180; i += 256) ws[i] = w[i];
  if (tid < 6) bs[tid] = bias[tid];
  __syncthreads();
  if (tid < 6){
    float inv  = 1.f / (64.f * 1020.f);
    float mean = stt[tid]*inv;
    float var  = stt[6+tid]*inv - mean*mean;
    float scl  = gamma[tid]*rsqrtf(var + 1e-5f);
    sc[tid] = scl; sh[tid] = beta[tid] - mean*scl;
  }
  __syncthreads();
  for (int i = tid; i < 6*T1; i += 256){
    int c = i / T1;
    float v = g_y1[b*6*T1 + i]*sc[c] + sh[c];
    xs[i] = fmaxf(v, 0.f);
  }
  __syncthreads();
  float s[6] = {0,0,0,0,0,0}, q[6] = {0,0,0,0,0,0};
  for (int t = tid; t < T2; t += 256){
    float acc[6];
    #pragma unroll
    for (int co = 0; co < 6; co++) acc[co] = bs[co];
    #pragma unroll
    for (int ci = 0; ci < 6; ci++){
      float xr[5];
      #pragma unroll
      for (int k = 0; k < 5; k++) xr[k] = xs[ci*T1 + t + k];
      #pragma unroll
      for (int co = 0; co < 6; co++){
        const float* wp = &ws[co*30 + ci*5];
        #pragma unroll
        for (int k = 0; k < 5; k++) acc[co] += xr[k]*wp[k];
      }
    }
    #pragma unroll
    for (int co = 0; co < 6; co++){
      g_y2[b*6*T2 + co*T2 + t] = acc[co];
      s[co] += acc[co]; q[co] += acc[co]*acc[co];
    }
  }
  int lane = tid & 31, wrp = tid >> 5;
  #pragma unroll
  for (int c = 0; c < 6; c++){
    float v = s[c], u = q[c];
    #pragma unroll
    for (int o = 16; o; o >>= 1){
      v += __shfl_down_sync(0xffffffffu, v, o);
      u += __shfl_down_sync(0xffffffffu, u, o);
    }
    if (lane == 0){ red[c][wrp] = v; red[6+c][wrp] = u; }
  }
  __syncthreads();
  if (tid < 12){
    float a = 0.f;
    #pragma unroll
    for (int w8 = 0; w8 < 8; w8++) a += red[tid][w8];
    g_part2[b*12 + tid] = a;
  }
}

// ---------------- bn2+relu -> attn projection -> feat[t][b][h] ----------------
__global__ void k_attn(const float* __restrict__ gamma, const float* __restrict__ beta,
                       const float* __restrict__ aw, const float* __restrict__ ab){
  __shared__ float xs[6*T2];
  __shared__ float stt[12];
  __shared__ float sc[6], sh[6];
  __shared__ float aws[72];
  __shared__ float abv[12];
  int b = blockIdx.x, tid = threadIdx.x;
  if (tid < 12){
    float a = 0.f;
    for (int bb = 0; bb < BB; bb++) a += g_part2[bb*12 + tid];
    stt[tid] = a;
  }
  if (tid < 72) aws[tid] = aw[tid];
  if (tid < 12) abv[tid] = ab[tid];
  __syncthreads();
  if (tid < 6){
    float inv  = 1.f / (64.f * 1016.f);
    float mean = stt[tid]*inv;
    float var  = stt[6+tid]*inv - mean*mean;
    float scl  = gamma[tid]*rsqrtf(var + 1e-5f);
    sc[tid] = scl; sh[tid] = beta[tid] - mean*scl;
  }
  __syncthreads();
  for (int i = tid; i < 6*T2; i += 256){
    int c = i / T2;
    float v = g_y2[b*6*T2 + i]*sc[c] + sh[c];
    xs[i] = fmaxf(v, 0.f);
  }
  __syncthreads();
  for (int i = tid; i < T2*HH; i += 256){
    int t = i / HH, h = i % HH;
    float acc = abv[h];
    #pragma unroll
    for (int c = 0; c < 6; c++) acc += xs[c*T2 + t]*aws[h*6 + c];
    g_feat[t*BH + b*12 + h] = fmaxf(acc, 0.f);
  }
}

// ---------------- pipelined 120-layer LSTM, k-split, 512 threads ----------
// 1 layer per CTA, 512 threads = 16 warps (4/SMSP vs 2 before).
// Lane group of 8 owns one batch element: b = tid>>3, sub = lane&7,
// q = sub>>1 (cells 3q..3q+2), half = sub&1 (k-split of the 24-wide dot):
//   half0 -> x-part (pairs 0..5), does all global loads/stores
//   half1 -> h-part (pairs 6..11), fed by the shfl gather
// Partial dots combined with one shfl_xor(s,1)+add per gate row.
// Sync = R8 per-warp release/acquire flags (best known).
__global__ void __launch_bounds__(512,1) k_lstm(const float* __restrict__ wih,
                                                const float* __restrict__ whh,
                                                const float* __restrict__ bih,
                                                const float* __restrict__ bhh){
  int l = blockIdx.x, tid = threadIdx.x;
  int lane = tid & 31;
  int wz   = tid >> 5;          // warp id 0..15
  int sub  = lane & 7;
  int q    = sub >> 1;          // cell quarter 0..3
  int half = sub & 1;           // k-half
  int b    = tid >> 3;          // batch element 0..63

  __shared__ __align__(16) u64 wpk[GG][12];  // packed {w_k,w_{k+1}} per gate row over [x;h]

  const float* wi = wih + l*576;
  const float* wh = whh + l*576;
  for (int i = tid; i < GG*12; i += 512){
    int gg = i / 12, kp = i % 12;
    float w0, w1;
    if (kp < 6){ w0 = wi[gg*12 + 2*kp];      w1 = wi[gg*12 + 2*kp + 1];  }
    else       { w0 = wh[gg*12 + 2*kp - 12]; w1 = wh[gg*12 + 2*kp - 11]; }
    wpk[gg][kp] = pk2(w0, w1);
  }
  __syncthreads();

  // register-cache gate-0 rows for this thread's cells + k-half: 3x6 u64
  u64 wr0[3][6];
  #pragma unroll
  for (int j = 0; j < 3; j++)
    #pragma unroll
    for (int k = 0; k < 6; k++)
      wr0[j][k] = wpk[3*q + j][6*half + k];

  // biases; gates 0,1,3 (sigmoid) pre-scaled by 0.5 for the tanh identity
  float br[12];
  #pragma unroll
  for (int j = 0; j < 3; j++){
    #pragma unroll
    for (int g4 = 0; g4 < 4; g4++){
      int row = g4*12 + 3*q + j;
      float bv = bih[l*GG + row] + bhh[l*GG + row];
      br[j*4+g4] = (g4 == 2) ? bv : 0.5f*bv;
    }
  }

  float c0 = 0.f, c1 = 0.f, c2 = 0.f;
  float hl0 = 0.f, hl1 = 0.f, hl2 = 0.f;
  float*       ringo = (l < LL-1) ? (g_ring + (size_t)l*(RING*BH)) : (float*)0;
  const float* ringi = (l > 0)    ? (g_ring + (size_t)(l-1)*(RING*BH)) : (const float*)0;
  const int* flag_in  = (l > 0)    ? &g_progress[(l-1)*NW + wz] : (const int*)0;
  const int* flag_out = (l < LL-1) ? &g_progress[(l+1)*NW + wz] : (const int*)0;
  int* flag_me = &g_progress[l*NW + wz];

  int last_in = 0, last_out = 0;
  int have = 0;
  float4 pa, pb, pc;

  for (int t = 0; t < T2; t++){
    // ---- gather previous h of this batch element via 8-lane shfl ----
    // (warp-collective; half1 consumes the values)
    float h_all[12];
    #pragma unroll
    for (int qp = 0; qp < 4; qp++){
      int src = (lane & ~7) | (qp << 1);
      h_all[3*qp+0] = __shfl_sync(0xffffffffu, hl0, src);
      h_all[3*qp+1] = __shfl_sync(0xffffffffu, hl1, src);
      h_all[3*qp+2] = __shfl_sync(0xffffffffu, hl2, src);
    }
    u64 xv[6];
    if (half){
      #pragma unroll
      for (int m = 0; m < 6; m++) xv[m] = pk2(h_all[2*m], h_all[2*m+1]);
    }

    // ---- input availability (cached, monotonic; warp-uniform) ----
    if (l > 0 && last_in < t+1){
      do { last_in = ld_acq(flag_in); } while (last_in < t+1);
    }
    int fut = last_in;
    if (l > 0 && t+1 < T2 && last_in < t+2) fut = ld_acq(flag_in);

    // ---- x-half loads (half0 lanes only) ----
    if (!half){
      float4 xa, xb, xc;
      if (have){ xa = pa; xb = pb; xc = pc; }
      else {
        const float* src = (l == 0) ? (g_feat + (size_t)t*BH + b*12)
                                    : (ringi + (size_t)(t & RM)*BH + b*12);
        xa = __ldcg((const float4*)(src));
        xb = __ldcg((const float4*)(src + 4));
        xc = __ldcg((const float4*)(src + 8));
      }
      xv[0] = pk2(xa.x, xa.y); xv[1] = pk2(xa.z, xa.w);
      xv[2] = pk2(xb.x, xb.y); xv[3] = pk2(xb.z, xb.w);
      xv[4] = pk2(xc.x, xc.y); xv[5] = pk2(xc.z, xc.w);
    }

    // ---- 12 gate rows: half-dot, then combine across the half pair ----
    float gv[12];
    // gate 0 from registers
    #pragma unroll
    for (int j = 0; j < 3; j++){
      u64 acc = 0ull;
      #pragma unroll
      for (int k = 0; k < 6; k++) ffma2(acc, wr0[j][k], xv[k]);
      float lo, hi; upk2(acc, lo, hi);
      float s = lo + hi;
      s += __shfl_xor_sync(0xffffffffu, s, 1);
      gv[j*4+0] = fmaf(s, 0.5f, br[j*4+0]);
    }
    // gates 1..3 from shared memory
    #pragma unroll
    for (int g4 = 1; g4 < 4; g4++){
      #pragma unroll
      for (int j = 0; j < 3; j++){
        const ulonglong2* wrow = (const ulonglong2*)(&wpk[g4*12 + 3*q + j][6*half]);
        u64 acc = 0ull;
        #pragma unroll
        for (int kq = 0; kq < 3; kq++){
          ulonglong2 wv = wrow[kq];
          ffma2(acc, wv.x, xv[2*kq]);
          ffma2(acc, wv.y, xv[2*kq+1]);
        }
        float lo, hi; upk2(acc, lo, hi);
        float s = lo + hi;
        s += __shfl_xor_sync(0xffffffffu, s, 1);
        gv[j*4+g4] = (g4 == 2) ? (s + br[j*4+g4])
                               : fmaf(s, 0.5f, br[j*4+g4]);
      }
    }

    // ---- prefetch input for t+1 (half0; warp-uniform guard) ----
    if (fut > last_in) last_in = fut;
    have = 0;
    if (t+1 < T2 && (l == 0 || last_in >= t+2)){
      if (!half){
        const float* src2 = (l == 0) ? (g_feat + (size_t)(t+1)*BH + b*12)
                                     : (ringi + (size_t)((t+1) & RM)*BH + b*12);
        pa = __ldcg((const float4*)(src2));
        pb = __ldcg((const float4*)(src2 + 4));
        pc = __ldcg((const float4*)(src2 + 8));
      }
      have = 1;
    }

    // ---- activations (HW tanh), computed by both halves (same gv) ----
    {
      float ig = fmaf(0.5f, tanhfast(gv[0]), 0.5f);
      float fg = fmaf(0.5f, tanhfast(gv[1]), 0.5f);
      float zg = tanhfast(gv[2]);
      float og = fmaf(0.5f, tanhfast(gv[3]), 0.5f);
      c0 = fg*c0 + ig*zg; hl0 = og*tanhfast(c0);
    }
    {
      float ig = fmaf(0.5f, tanhfast(gv[4]), 0.5f);
      float fg = fmaf(0.5f, tanhfast(gv[5]), 0.5f);
      float zg = tanhfast(gv[6]);
      float og = fmaf(0.5f, tanhfast(gv[7]), 0.5f);
      c1 = fg*c1 + ig*zg; hl1 = og*tanhfast(c1);
    }
    {
      float ig = fmaf(0.5f, tanhfast(gv[8]), 0.5f);
      float fg = fmaf(0.5f, tanhfast(gv[9]), 0.5f);
      float zg = tanhfast(gv[10]);
      float og = fmaf(0.5f, tanhfast(gv[11]), 0.5f);
      c2 = fg*c2 + ig*zg; hl2 = og*tanhfast(c2);
    }

    // ---- publish (half0 stores; backpressure warp-uniform) ----
    if (l < LL-1){
      if (t >= RING && last_out + RING < t+1){
        do { last_out = ld_acq(flag_out); } while (last_out + RING < t+1);
      }
      if (!half){
        float* dst = ringo + (size_t)(t & RM)*BH + b*12 + 3*q;
        __stcg(dst,     hl0);
        __stcg(dst + 1, hl1);
        __stcg(dst + 2, hl2);
      }
    }
    __syncwarp();
    if (lane == 0) st_rel(flag_me, t+1);
  }

  if (!half){
    int base = l*BH + b*12 + 3*q;
    g_hlast[base]     = hl0;
    g_hlast[base + 1] = hl1;
    g_hlast[base + 2] = hl2;
  }
}

// ---------------- head: lin1/lin2 -> out, mu, softplus(sigma) ----------------
__global__ void k_head(const float* __restrict__ l1w, const float* __restrict__ l1b,
                       const float* __restrict__ l2w, const float* __restrict__ l2b,
                       const float* __restrict__ muw, const float* __restrict__ mub,
                       const float* __restrict__ sgw, const float* __restrict__ sgb,
                       float* __restrict__ out){
  int idx = blockIdx.x*blockDim.x + threadIdx.x;
  if (idx >= BB*LL) return;
  int b = idx / LL, l = idx % LL;
  const float* hv = g_hlast + l*BH + b*12;
  float h0[12], h1[12], h2[12];
  #pragma unroll
  for (int k = 0; k < 12; k++) h0[k] = hv[k];
  #pragma unroll
  for (int i = 0; i < 12; i++){
    float a = l1b[i];
    #pragma unroll
    for (int j = 0; j < 12; j++) a += l1w[i*12+j]*h0[j];
    h1[i] = fmaxf(a, 0.f);
  }
  #pragma unroll
  for (int i = 0; i < 12; i++){
    float a = l2b[i];
    #pragma unroll
    for (int j = 0; j < 12; j++) a += l2w[i*12+j]*h1[j];
    h2[i] = fmaxf(a, 0.f);
  }
  int base = (b*LL + l)*12;
  #pragma unroll
  for (int i = 0; i < 12; i++) out[base + i] = h2[i];
  #pragma unroll
  for (int i = 0; i < 12; i++){
    float a = mub[i];
    #pragma unroll
    for (int j = 0; j < 12; j++) a += muw[i*12+j]*h2[j];
    out[OUTSZ + base + i] = a;
  }
  #pragma unroll
  for (int i = 0; i < 12; i++){
    float a = sgb[i];
    #pragma unroll
    for (int j = 0; j < 12; j++) a += sgw[i*12+j]*h2[j];
    out[2*OUTSZ + base + i] = fmaxf(a, 0.f) + log1pf(__expf(-fabsf(a)));
  }
}

extern "C" void kernel_launch(void* const* d_in, const int* in_sizes, int n_in,
                              void* d_out, int out_size) {
  const float* x     = (const float*)d_in[0];
  const float* c1w   = (const float*)d_in[1];
  const float* c1b   = (const float*)d_in[2];
  const float* bn1g  = (const float*)d_in[3];
  const float* bn1b  = (const float*)d_in[4];
  const float* c2w   = (const float*)d_in[5];
  const float* c2b   = (const float*)d_in[6];
  const float* bn2g  = (const float*)d_in[7];
  const float* bn2b  = (const float*)d_in[8];
  const float* aw    = (const float*)d_in[9];
  const float* ab    = (const float*)d_in[10];
  const float* wih   = (const float*)d_in[11];
  const float* whh   = (const float*)d_in[12];
  const float* bih   = (const float*)d_in[13];
  const float* bhh   = (const float*)d_in[14];
  const float* l1w   = (const float*)d_in[15];
  const float* l1b   = (const float*)d_in[16];
  const float* l2w   = (const float*)d_in[17];
  const float* l2b   = (const float*)d_in[18];
  const float* muw   = (const float*)d_in[19];
  const float* mub   = (const float*)d_in[20];
  const float* sgw   = (const float*)d_in[21];
  const float* sgb   = (const float*)d_in[22];
  float* out = (float*)d_out;

  k_conv1<<<BB, 256>>>(x, c1w, c1b);
  k_conv2<<<BB, 256>>>(c2w, c2b, bn1g, bn1b);
  k_attn<<<BB, 256>>>(bn2g, bn2b, aw, ab);
  k_lstm<<<LL, 512>>>(wih, whh, bih, bhh);
  k_head<<<(BB*LL + 127)/128, 128>>>(l1w, l1b, l2w, l2b, muw, mub, sgw, sgb, out);
}

// round 17
// speedup vs baseline: 1.1313x; 1.1005x over previous
#include <cuda_runtime.h>

typedef unsigned long long u64;
typedef unsigned int u32;

#define BB   64
#define TIN  1024
#define T1   1020
#define T2   1016
#define HH   12
#define LL   120
#define GG   48
#define RING 64
#define RM   (RING-1)
#define DRING 8
#define DRM  (DRING-1)
#define BH   (BB*HH)     /* 768 */
#define OUTSZ (BB*LL*HH) /* 92160 */
#define NW   8           /* warps per layer CTA */
#define CLS  8           /* layers per cluster */

// ---------------- device scratch (static, no allocation) ----------------
__device__ float g_y1[BB*6*T1];
__device__ float g_y2[BB*6*T2];
__device__ float g_part1[BB*12];
__device__ float g_part2[BB*12];
__device__ float g_feat[T2*BH];
__device__ float g_ring[(LL-1)*RING*BH];
__device__ float g_hlast[LL*BH];
__device__ int   g_progress[LL*NW];

// ---------------- helpers ----------------
__device__ __forceinline__ int ld_acq(const int* p){
  int v; asm volatile("ld.acquire.gpu.b32 %0, [%1];" : "=r"(v) : "l"(p)); return v;
}
__device__ __forceinline__ void st_rel(int* p, int v){
  asm volatile("st.release.gpu.b32 [%0], %1;" :: "l"(p), "r"(v));
}
__device__ __forceinline__ u32 smem_u32(const void* p){
  return (u32)__cvta_generic_to_shared(p);
}
__device__ __forceinline__ u32 mapa_u32(u32 a, int r){
  u32 d; asm("mapa.shared::cluster.u32 %0, %1, %2;" : "=r"(d) : "r"(a), "r"(r)); return d;
}
__device__ __forceinline__ void st_ds_f32(u32 a, float v){
  asm volatile("st.shared::cluster.f32 [%0], %1;" :: "r"(a), "f"(v));
}
__device__ __forceinline__ void st_rel_ds(u32 a, int v){
  asm volatile("st.release.cluster.shared::cluster.b32 [%0], %1;" :: "r"(a), "r"(v));
}
__device__ __forceinline__ int ld_acq_sh(const int* p){
  int v; u32 a = smem_u32(p);
  asm volatile("ld.acquire.cluster.shared::cta.b32 %0, [%1];" : "=r"(v) : "r"(a));
  return v;
}
__device__ __forceinline__ u64 pk2(float lo, float hi){
  u64 r; asm("mov.b64 %0, {%1, %2};" : "=l"(r) : "f"(lo), "f"(hi)); return r;
}
__device__ __forceinline__ void upk2(u64 v, float& lo, float& hi){
  asm("mov.b64 {%0, %1}, %2;" : "=f"(lo), "=f"(hi) : "l"(v));
}
__device__ __forceinline__ void ffma2(u64& acc, u64 a, u64 b){
  asm("fma.rn.f32x2 %0, %1, %2, %0;" : "+l"(acc) : "l"(a), "l"(b));
}
// hardware tanh (sm_75+): single MUFU op
__device__ __forceinline__ float tanhfast(float x){
  float y; asm("tanh.approx.f32 %0, %1;" : "=f"(y) : "f"(x)); return y;
}

// ---------------- conv1 + batch-stat partials (+ pipeline-flag reset) ------
__global__ void k_conv1(const float* __restrict__ x, const float* __restrict__ w,
                        const float* __restrict__ bias){
  __shared__ float xs[6*TIN];
  __shared__ float ws[180];
  __shared__ float bs[6];
  __shared__ float red[12][8];
  int b = blockIdx.x, tid = threadIdx.x;
  if (b == 0){                       // flag reset (read only by later k_lstm)
    for (int i = tid; i < LL*NW; i += 256) g_progress[i] = 0;
  }
  for (int i = tid; i < 6*TIN; i += 256) xs[i] = x[b*6*TIN + i];
  for (int i = tid; i < 180;   i += 256) ws[i] = w[i];
  if (tid < 6) bs[tid] = bias[tid];
  __syncthreads();
  float s[6] = {0,0,0,0,0,0}, q[6] = {0,0,0,0,0,0};
  for (int t = tid; t < T1; t += 256){
    float acc[6];
    #pragma unroll
    for (int co = 0; co < 6; co++) acc[co] = bs[co];
    #pragma unroll
    for (int ci = 0; ci < 6; ci++){
      float xr[5];
      #pragma unroll
      for (int k = 0; k < 5; k++) xr[k] = xs[ci*TIN + t + k];
      #pragma unroll
      for (int co = 0; co < 6; co++){
        const float* wp = &ws[co*30 + ci*5];
        #pragma unroll
        for (int k = 0; k < 5; k++) acc[co] += xr[k]*wp[k];
      }
    }
    #pragma unroll
    for (int co = 0; co < 6; co++){
      g_y1[b*6*T1 + co*T1 + t] = acc[co];
      s[co] += acc[co]; q[co] += acc[co]*acc[co];
    }
  }
  int lane = tid & 31, wrp = tid >> 5;
  #pragma unroll
  for (int c = 0; c < 6; c++){
    float v = s[c], u = q[c];
    #pragma unroll
    for (int o = 16; o; o >>= 1){
      v += __shfl_down_sync(0xffffffffu, v, o);
      u += __shfl_down_sync(0xffffffffu, u, o);
    }
    if (lane == 0){ red[c][wrp] = v; red[6+c][wrp] = u; }
  }
  __syncthreads();
  if (tid < 12){
    float a = 0.f;
    #pragma unroll
    for (int w8 = 0; w8 < 8; w8++) a += red[tid][w8];
    g_part1[b*12 + tid] = a;
  }
}

// ---------------- bn1+relu -> conv2 + stat partials ----------------
__global__ void k_conv2(const float* __restrict__ w, const float* __restrict__ bias,
                        const float* __restrict__ gamma, const float* __restrict__ beta){
  __shared__ float xs[6*T1];
  __shared__ float ws[180];
  __shared__ float bs[6];
  __shared__ float stt[12];
  __shared__ float sc[6], sh[6];
  __shared__ float red[12][8];
  int b = blockIdx.x, tid = threadIdx.x;
  if (tid < 12){
    float a = 0.f;
    for (int bb = 0; bb < BB; bb++) a += g_part1[bb*12 + tid];
    stt[tid] = a;
  }
  for (int i = tid; i < 180; i += 256) ws[i] = w[i];
  if (tid < 6) bs[tid] = bias[tid];
  __syncthreads();
  if (tid < 6){
    float inv  = 1.f / (64.f * 1020.f);
    float mean = stt[tid]*inv;
    float var  = stt[6+tid]*inv - mean*mean;
    float scl  = gamma[tid]*rsqrtf(var + 1e-5f);
    sc[tid] = scl; sh[tid] = beta[tid] - mean*scl;
  }
  __syncthreads();
  for (int i = tid; i < 6*T1; i += 256){
    int c = i / T1;
    float v = g_y1[b*6*T1 + i]*sc[c] + sh[c];
    xs[i] = fmaxf(v, 0.f);
  }
  __syncthreads();
  float s[6] = {0,0,0,0,0,0}, q[6] = {0,0,0,0,0,0};
  for (int t = tid; t < T2; t += 256){
    float acc[6];
    #pragma unroll
    for (int co = 0; co < 6; co++) acc[co] = bs[co];
    #pragma unroll
    for (int ci = 0; ci < 6; ci++){
      float xr[5];
      #pragma unroll
      for (int k = 0; k < 5; k++) xr[k] = xs[ci*T1 + t + k];
      #pragma unroll
      for (int co = 0; co < 6; co++){
        const float* wp = &ws[co*30 + ci*5];
        #pragma unroll
        for (int k = 0; k < 5; k++) acc[co] += xr[k]*wp[k];
      }
    }
    #pragma unroll
    for (int co = 0; co < 6; co++){
      g_y2[b*6*T2 + co*T2 + t] = acc[co];
      s[co] += acc[co]; q[co] += acc[co]*acc[co];
    }
  }
  int lane = tid & 31, wrp = tid >> 5;
  #pragma unroll
  for (int c = 0; c < 6; c++){
    float v = s[c], u = q[c];
    #pragma unroll
    for (int o = 16; o; o >>= 1){
      v += __shfl_down_sync(0xffffffffu, v, o);
      u += __shfl_down_sync(0xffffffffu, u, o);
    }
    if (lane == 0){ red[c][wrp] = v; red[6+c][wrp] = u; }
  }
  __syncthreads();
  if (tid < 12){
    float a = 0.f;
    #pragma unroll
    for (int w8 = 0; w8 < 8; w8++) a += red[tid][w8];
    g_part2[b*12 + tid] = a;
  }
}

// ---------------- bn2+relu -> attn projection -> feat[t][b][h] ----------------
__global__ void k_attn(const float* __restrict__ gamma, const float* __restrict__ beta,
                       const float* __restrict__ aw, const float* __restrict__ ab){
  __shared__ float xs[6*T2];
  __shared__ float stt[12];
  __shared__ float sc[6], sh[6];
  __shared__ float aws[72];
  __shared__ float abv[12];
  int b = blockIdx.x, tid = threadIdx.x;
  if (tid < 12){
    float a = 0.f;
    for (int bb = 0; bb < BB; bb++) a += g_part2[bb*12 + tid];
    stt[tid] = a;
  }
  if (tid < 72) aws[tid] = aw[tid];
  if (tid < 12) abv[tid] = ab[tid];
  __syncthreads();
  if (tid < 6){
    float inv  = 1.f / (64.f * 1016.f);
    float mean = stt[tid]*inv;
    float var  = stt[6+tid]*inv - mean*mean;
    float scl  = gamma[tid]*rsqrtf(var + 1e-5f);
    sc[tid] = scl; sh[tid] = beta[tid] - mean*scl;
  }
  __syncthreads();
  for (int i = tid; i < 6*T2; i += 256){
    int c = i / T2;
    float v = g_y2[b*6*T2 + i]*sc[c] + sh[c];
    xs[i] = fmaxf(v, 0.f);
  }
  __syncthreads();
  for (int i = tid; i < T2*HH; i += 256){
    int t = i / HH, h = i % HH;
    float acc = abv[h];
    #pragma unroll
    for (int c = 0; c < 6; c++) acc += xs[c*T2 + t]*aws[h*6 + c];
    g_feat[t*BH + b*12 + h] = fmaxf(acc, 0.f);
  }
}

// ---------------- pipelined 120-layer LSTM, DSMEM clusters ----------------
// 1 layer per CTA, clusters of 8 layers. Intra-cluster edges: producer
// pushes h into the consumer's smem ring (st.shared::cluster) and releases a
// flag in consumer smem -> consumer polls/loads LOCAL smem (~30 cyc instead
// of ~600-cyc L2 round trips). Cluster-boundary edges keep the proven R8
// global-ring path. Lane-group of 4 owns one batch element (b = tid>>2,
// q = tid&3, cells 3q..3q+2); h exchanged via shfl. tanh.approx activations.
__global__ void __launch_bounds__(256,1) __cluster_dims__(CLS,1,1)
k_lstm(const float* __restrict__ wih, const float* __restrict__ whh,
       const float* __restrict__ bih, const float* __restrict__ bhh){
  int l = blockIdx.x, tid = threadIdx.x;
  int lane = tid & 31;
  int wz   = tid >> 5;          // warp id 0..7
  int q    = lane & 3;          // quarter within batch group
  int b    = tid >> 2;          // batch element 0..63
  int rank = l & (CLS-1);       // cluster rank

  const bool cons_ds = (l > 0)    && (rank != 0);      // consume via DSMEM
  const bool prod_ds = (l < LL-1) && (rank != CLS-1);  // produce via DSMEM
  const bool cons_gl = (l > 0)    && (rank == 0);      // cluster head: global
  const bool prod_gl = (l < LL-1) && (rank == CLS-1);  // cluster tail: global

  __shared__ __align__(16) u64   wpk[GG][12];
  __shared__ __align__(16) float ring_s[DRING][BH];   // input ring (written by rank-1)
  __shared__ int in_flag[NW];     // producer progress (pushed by rank-1)
  __shared__ int cons_prog[NW];   // consumer progress (pushed by rank+1)

  const float* wi = wih + l*576;
  const float* wh = whh + l*576;
  for (int i = tid; i < GG*12; i += 256){
    int gg = i / 12, kp = i % 12;
    float w0, w1;
    if (kp < 6){ w0 = wi[gg*12 + 2*kp];      w1 = wi[gg*12 + 2*kp + 1];  }
    else       { w0 = wh[gg*12 + 2*kp - 12]; w1 = wh[gg*12 + 2*kp - 11]; }
    wpk[gg][kp] = pk2(w0, w1);
  }
  if (tid < NW){ in_flag[tid] = 0; cons_prog[tid] = 0; }
  __syncthreads();
  // all CTAs of the cluster must have flags initialized before any DSMEM write
  asm volatile("barrier.cluster.arrive.aligned;" ::: "memory");
  asm volatile("barrier.cluster.wait.aligned;"   ::: "memory");

  // register-cache gate-0 rows only (3 rows x 12 u64 = 36 regs)
  u64 wr[3][12];
  #pragma unroll
  for (int j = 0; j < 3; j++)
    #pragma unroll
    for (int k = 0; k < 12; k++)
      wr[j][k] = wpk[3*q + j][k];

  // biases; gates 0,1,3 (sigmoid) pre-scaled by 0.5 for the tanh identity
  float br[12];
  #pragma unroll
  for (int j = 0; j < 3; j++){
    #pragma unroll
    for (int g4 = 0; g4 < 4; g4++){
      int row = g4*12 + 3*q + j;
      float bv = bih[l*GG + row] + bhh[l*GG + row];
      br[j*4+g4] = (g4 == 2) ? bv : 0.5f*bv;
    }
  }

  // remote smem addresses (computed once)
  u32 rring = 0, rflag = 0, rprog = 0;
  if (prod_ds){
    rring = mapa_u32(smem_u32(&ring_s[0][0]), rank+1);
    rflag = mapa_u32(smem_u32(&in_flag[wz]),  rank+1);
  }
  if (cons_ds){
    rprog = mapa_u32(smem_u32(&cons_prog[wz]), rank-1);
  }

  float c0 = 0.f, c1 = 0.f, c2 = 0.f;
  float hl0 = 0.f, hl1 = 0.f, hl2 = 0.f;
  const float* ringi = cons_gl ? (g_ring + (size_t)(l-1)*(RING*BH)) : (const float*)0;
  float*       ringo = prod_gl ? (g_ring + (size_t)l*(RING*BH))     : (float*)0;
  const int* flag_in_g  = cons_gl ? &g_progress[(l-1)*NW + wz] : (const int*)0;
  const int* flag_out_g = prod_gl ? &g_progress[(l+1)*NW + wz] : (const int*)0;
  int* flag_me = &g_progress[l*NW + wz];

  int last_in = 0, last_out = 0;
  int have = 0;
  float4 pa, pb, pc;

  for (int t = 0; t < T2; t++){
    // ---- gather previous h of this batch element via 4-lane shfl ----
    float h_all[12];
    #pragma unroll
    for (int qp = 0; qp < 4; qp++){
      int src = (lane & ~3) | qp;
      h_all[3*qp+0] = __shfl_sync(0xffffffffu, hl0, src);
      h_all[3*qp+1] = __shfl_sync(0xffffffffu, hl1, src);
      h_all[3*qp+2] = __shfl_sync(0xffffffffu, hl2, src);
    }
    u64 xv[12];
    #pragma unroll
    for (int m = 0; m < 6; m++) xv[6+m] = pk2(h_all[2*m], h_all[2*m+1]);

    // ---- input ----
    float4 xa, xb, xc;
    int fut = last_in;
    if (cons_ds){
      if (last_in < t+1){
        do { last_in = ld_acq_sh(&in_flag[wz]); } while (last_in < t+1);
      }
      const float4* s4 = (const float4*)&ring_s[t & DRM][b*12];
      xa = s4[0]; xb = s4[1]; xc = s4[2];
    } else {
      if (cons_gl && last_in < t+1){
        do { last_in = ld_acq(flag_in_g); } while (last_in < t+1);
      }
      if (cons_gl && t+1 < T2 && last_in < t+2) fut = ld_acq(flag_in_g);
      if (have){ xa = pa; xb = pb; xc = pc; }
      else {
        const float* src = (l == 0) ? (g_feat + (size_t)t*BH + b*12)
                                    : (ringi + (size_t)(t & RM)*BH + b*12);
        xa = __ldcg((const float4*)(src));
        xb = __ldcg((const float4*)(src + 4));
        xc = __ldcg((const float4*)(src + 8));
      }
    }
    xv[0] = pk2(xa.x, xa.y); xv[1] = pk2(xa.z, xa.w);
    xv[2] = pk2(xb.x, xb.y); xv[3] = pk2(xb.z, xb.w);
    xv[4] = pk2(xc.x, xc.y); xv[5] = pk2(xc.z, xc.w);

    // ---- 12 gate pre-activations: gate 0 from registers ----
    float gv[12];
    #pragma unroll
    for (int j = 0; j < 3; j++){
      u64 acc = 0ull;
      #pragma unroll
      for (int k = 0; k < 12; k++) ffma2(acc, wr[j][k], xv[k]);
      float lo, hi; upk2(acc, lo, hi);
      gv[j*4+0] = fmaf(lo + hi, 0.5f, br[j*4+0]);
    }
    // ---- gates 1..3 from shared memory ----
    #pragma unroll
    for (int g4 = 1; g4 < 4; g4++){
      #pragma unroll
      for (int j = 0; j < 3; j++){
        const ulonglong2* wrow = (const ulonglong2*)(&wpk[g4*12 + 3*q + j][0]);
        u64 acc = 0ull;
        #pragma unroll
        for (int kq = 0; kq < 6; kq++){
          ulonglong2 wv = wrow[kq];
          ffma2(acc, wv.x, xv[2*kq]);
          ffma2(acc, wv.y, xv[2*kq+1]);
        }
        float lo, hi; upk2(acc, lo, hi);
        gv[j*4+g4] = (g4 == 2) ? (lo + hi + br[j*4+g4])
                               : fmaf(lo + hi, 0.5f, br[j*4+g4]);
      }
    }

    // ---- prefetch (global consumers only) ----
    if (!cons_ds){
      if (fut > last_in) last_in = fut;
      have = 0;
      if (t+1 < T2 && (l == 0 || last_in >= t+2)){
        const float* src2 = (l == 0) ? (g_feat + (size_t)(t+1)*BH + b*12)
                                     : (ringi + (size_t)((t+1) & RM)*BH + b*12);
        pa = __ldcg((const float4*)(src2));
        pb = __ldcg((const float4*)(src2 + 4));
        pc = __ldcg((const float4*)(src2 + 8));
        have = 1;
      }
    }

    // ---- activations (HW tanh) + cell update ----
    {
      float ig = fmaf(0.5f, tanhfast(gv[0]), 0.5f);
      float fg = fmaf(0.5f, tanhfast(gv[1]), 0.5f);
      float zg = tanhfast(gv[2]);
      float og = fmaf(0.5f, tanhfast(gv[3]), 0.5f);
      c0 = fg*c0 + ig*zg; hl0 = og*tanhfast(c0);
    }
    {
      float ig = fmaf(0.5f, tanhfast(gv[4]), 0.5f);
      float fg = fmaf(0.5f, tanhfast(gv[5]), 0.5f);
      float zg = tanhfast(gv[6]);
      float og = fmaf(0.5f, tanhfast(gv[7]), 0.5f);
      c1 = fg*c1 + ig*zg; hl1 = og*tanhfast(c1);
    }
    {
      float ig = fmaf(0.5f, tanhfast(gv[8]), 0.5f);
      float fg = fmaf(0.5f, tanhfast(gv[9]), 0.5f);
      float zg = tanhfast(gv[10]);
      float og = fmaf(0.5f, tanhfast(gv[11]), 0.5f);
      c2 = fg*c2 + ig*zg; hl2 = og*tanhfast(c2);
    }

    // ---- publish ----
    if (prod_ds){
      // slot reuse: need consumer progress >= t+1-DRING before overwriting
      if (t >= DRING && last_out < t+1-DRING){
        do { last_out = ld_acq_sh(&cons_prog[wz]); } while (last_out < t+1-DRING);
      }
      u32 da = rring + (u32)(((t & DRM)*BH + b*12 + 3*q) * 4);
      st_ds_f32(da,     hl0);
      st_ds_f32(da + 4, hl1);
      st_ds_f32(da + 8, hl2);
      __syncwarp();
      if (lane == 0) st_rel_ds(rflag, t+1);
    }
    if (prod_gl){
      if (t >= RING && last_out + RING < t+1){
        do { last_out = ld_acq(flag_out_g); } while (last_out + RING < t+1);
      }
      float* dst = ringo + (size_t)(t & RM)*BH + b*12 + 3*q;
      __stcg(dst,     hl0);
      __stcg(dst + 1, hl1);
      __stcg(dst + 2, hl2);
    }
    __syncwarp();
    if (lane == 0){
      st_rel(flag_me, t+1);                    // global progress (heads/tails use it)
      if (cons_ds) st_rel_ds(rprog, t+1);      // backpressure to DSMEM producer
    }
  }

  int base = l*BH + b*12 + 3*q;
  g_hlast[base]     = hl0;
  g_hlast[base + 1] = hl1;
  g_hlast[base + 2] = hl2;

  // no CTA may exit while peers can still write its smem
  asm volatile("barrier.cluster.arrive.aligned;" ::: "memory");
  asm volatile("barrier.cluster.wait.aligned;"   ::: "memory");
}

// ---------------- head: lin1/lin2 -> out, mu, softplus(sigma) ----------------
__global__ void k_head(const float* __restrict__ l1w, const float* __restrict__ l1b,
                       const float* __restrict__ l2w, const float* __restrict__ l2b,
                       const float* __restrict__ muw, const float* __restrict__ mub,
                       const float* __restrict__ sgw, const float* __restrict__ sgb,
                       float* __restrict__ out){
  int idx = blockIdx.x*blockDim.x + threadIdx.x;
  if (idx >= BB*LL) return;
  int b = idx / LL, l = idx % LL;
  const float* hv = g_hlast + l*BH + b*12;
  float h0[12], h1[12], h2[12];
  #pragma unroll
  for (int k = 0; k < 12; k++) h0[k] = hv[k];
  #pragma unroll
  for (int i = 0; i < 12; i++){
    float a = l1b[i];
    #pragma unroll
    for (int j = 0; j < 12; j++) a += l1w[i*12+j]*h0[j];
    h1[i] = fmaxf(a, 0.f);
  }
  #pragma unroll
  for (int i = 0; i < 12; i++){
    float a = l2b[i];
    #pragma unroll
    for (int j = 0; j < 12; j++) a += l2w[i*12+j]*h1[j];
    h2[i] = fmaxf(a, 0.f);
  }
  int base = (b*LL + l)*12;
  #pragma unroll
  for (int i = 0; i < 12; i++) out[base + i] = h2[i];
  #pragma unroll
  for (int i = 0; i < 12; i++){
    float a = mub[i];
    #pragma unroll
    for (int j = 0; j < 12; j++) a += muw[i*12+j]*h2[j];
    out[OUTSZ + base + i] = a;
  }
  #pragma unroll
  for (int i = 0; i < 12; i++){
    float a = sgb[i];
    #pragma unroll
    for (int j = 0; j < 12; j++) a += sgw[i*12+j]*h2[j];
    out[2*OUTSZ + base + i] = fmaxf(a, 0.f) + log1pf(__expf(-fabsf(a)));
  }
}

extern "C" void kernel_launch(void* const* d_in, const int* in_sizes, int n_in,
                              void* d_out, int out_size) {
  const float* x     = (const float*)d_in[0];
  const float* c1w   = (const float*)d_in[1];
  const float* c1b   = (const float*)d_in[2];
  const float* bn1g  = (const float*)d_in[3];
  const float* bn1b  = (const float*)d_in[4];
  const float* c2w   = (const float*)d_in[5];
  const float* c2b   = (const float*)d_in[6];
  const float* bn2g  = (const float*)d_in[7];
  const float* bn2b  = (const float*)d_in[8];
  const float* aw    = (const float*)d_in[9];
  const float* ab    = (const float*)d_in[10];
  const float* wih   = (const float*)d_in[11];
  const float* whh   = (const float*)d_in[12];
  const float* bih   = (const float*)d_in[13];
  const float* bhh   = (const float*)d_in[14];
  const float* l1w   = (const float*)d_in[15];
  const float* l1b   = (const float*)d_in[16];
  const float* l2w   = (const float*)d_in[17];
  const float* l2b   = (const float*)d_in[18];
  const float* muw   = (const float*)d_in[19];
  const float* mub   = (const float*)d_in[20];
  const float* sgw   = (const float*)d_in[21];
  const float* sgb   = (const float*)d_in[22];
  float* out = (float*)d_out;

  k_conv1<<<BB, 256>>>(x, c1w, c1b);
  k_conv2<<<BB, 256>>>(c2w, c2b, bn1g, bn1b);
  k_attn<<<BB, 256>>>(bn2g, bn2b, aw, ab);
  k_lstm<<<LL, 256>>>(wih, whh, bih, bhh);
  k_head<<<(BB*LL + 127)/128, 128>>>(l1w, l1b, l2w, l2b, muw, mub, sgw, sgb, out);
}